// round 14
// baseline (speedup 1.0000x reference)
#include <cuda_runtime.h>
#include <cuda_fp16.h>
#include <math.h>
#include <stdint.h>

// VectorQuantizer: fp16x2 HFMA2 screen (2 dims/inst) + exact fp32 rescore.
// N=131072 rows (dim 64) vs 512 codes. Persistent 148x512.
// Out (fp32): [0,8388608) quantized_st; [8388608,8519680) codes;
//             then commitment*0.25, codebook_loss, perplexity.
// Screen ranks by fp16(c2 - 2*dot); worst-case screen-vs-exact deviation
// bounded by E<=~5e-3, window WIN=2.2e-2 >= 2E (2x margin). Candidates
// within window of screen-min are rescored with the bitwise-exact reference
// pipeline (sequential fma chain, round((x2-2m)+c2), first-min).
// (Resubmission: previous round was a broker infra failure, no signal.)
#define K_CODES 512
#define DIMV 64
#define NROWS 131072
#define TPB 512
#define NBLK 148
#define ROWS_PER_BLK ((NROWS + NBLK - 1) / NBLK)   // 886
#define NTRK 12
#define WIN 2.2e-2f
#define MINUS2H2 0xC000C000u   // fp16x2 (-2,-2)

typedef unsigned long long u64;
typedef unsigned int u32;

// smem float-word offsets
#define W_SCB  0                        // fp32 codebook 512*64
#define W_SCH  (512 * 64)               // fp16x2 codebook 512*32 u32
#define W_SC2  (W_SCH + 512 * 32)       // fp32 c2 [512]
#define W_C2H  (W_SC2 + 512)            // fp16 c2 pairs [256 u32]
#define W_HIST (W_C2H + 256)            // int [512]
#define W_SRED (W_HIST + 512)           // float [TPB]
#define SMEM_WORDS (W_SRED + TPB)

__device__ double g_sqsum;
__device__ int g_counts[K_CODES];

__device__ __forceinline__ u32 hfma2u(u32 a, u32 b, u32 c) {
    u32 r;
    asm("fma.rn.f16x2 %0, %1, %2, %3;" : "=r"(r) : "r"(a), "r"(b), "r"(c));
    return r;
}
__device__ __forceinline__ u32 hadd2u(u32 a, u32 b) {
    u32 r;
    asm("add.rn.f16x2 %0, %1, %2;" : "=r"(r) : "r"(a), "r"(b));
    return r;
}
__device__ __forceinline__ u32 packh2(float a, float b) {
    __half2 h = __floats2half2_rn(a, b);
    return *(u32*)&h;
}

__global__ void vq_init_kernel() {
    int t = blockIdx.x * blockDim.x + threadIdx.x;
    if (t == 0) g_sqsum = 0.0;
    if (t < K_CODES) g_counts[t] = 0;
}

// sorted top-NTRK insert (ascending keys); fully unrolled -> registers.
__device__ __forceinline__ void trk_insert(u32 (&t)[NTRK], u32 key) {
    if (key < t[NTRK - 1]) {
        #pragma unroll
        for (int i = NTRK - 1; i >= 1; --i)
            t[i] = (key < t[i - 1]) ? t[i - 1] : ((key < t[i]) ? key : t[i]);
        t[0] = (key < t[0]) ? key : t[0];
    }
}

__global__ __launch_bounds__(TPB, 1)
void vq_main_kernel(const float* __restrict__ latents,
                    const float* __restrict__ codebook,
                    float* __restrict__ out) {
    extern __shared__ float smem[];
    float* scb  = smem + W_SCB;
    u32*  sch   = (u32*)(smem + W_SCH);
    float* sc2  = smem + W_SC2;
    u32*  c2h   = (u32*)(smem + W_C2H);
    int*  shist = (int*)(smem + W_HIST);
    float* sred = smem + W_SRED;

    const int tid = threadIdx.x;

    // ---- prologue: fp32 codebook + fp16x2 codebook in one pass ----
    const float4* cb4 = (const float4*)codebook;
    for (int g = tid; g < K_CODES * 16; g += TPB) {
        float4 v = cb4[g];
        ((float4*)scb)[g] = v;
        sch[2 * g]     = packh2(v.x, v.y);
        sch[2 * g + 1] = packh2(v.z, v.w);
    }
    for (int k = tid; k < K_CODES; k += TPB) shist[k] = 0;
    __syncthreads();
    // c2 in reference rounding order, plus fp16 copy (half k of c2h words).
    for (int k = tid; k < K_CODES; k += TPB) {
        float s = 0.f;
        const float* c = scb + k * DIMV;
        #pragma unroll
        for (int d = 0; d < DIMV; ++d) s = __fadd_rn(s, __fmul_rn(c[d], c[d]));
        sc2[k] = s;
        ((__half*)c2h)[k] = __float2half_rn(s);
    }
    __syncthreads();

    const int row0 = blockIdx.x * ROWS_PER_BLK;
    const int rowEnd = min(row0 + ROWS_PER_BLK, NROWS);
    float sqAcc = 0.f;

    for (int row = row0 + tid; row < rowEnd; row += TPB) {
        const float4* lp = (const float4*)(latents + (size_t)row * DIMV);

        // latent row as 32 fp16x2 regs
        u32 x16[32];
        #pragma unroll
        for (int i = 0; i < 16; ++i) {
            float4 v = lp[i];
            x16[2 * i]     = packh2(v.x, v.y);
            x16[2 * i + 1] = packh2(v.z, v.w);
        }

        // ---- screen: 64 groups of 8 codes; 32 HFMA2 per code ----
        u32 trk[NTRK];
        #pragma unroll
        for (int i = 0; i < NTRK; ++i) trk[i] = 0xFFFFFFFFu;

        for (int kb = 0; kb < K_CODES; kb += 8) {
            u32 acc[8];
            #pragma unroll
            for (int j = 0; j < 8; ++j) acc[j] = 0u;
            #pragma unroll
            for (int ib = 0; ib < 8; ++ib) {
                const u32 xa = x16[4 * ib + 0], xb = x16[4 * ib + 1];
                const u32 xc = x16[4 * ib + 2], xd = x16[4 * ib + 3];
                #pragma unroll
                for (int j = 0; j < 8; ++j) {
                    const uint4 cc = *(const uint4*)(sch + (kb + j) * 32 + 4 * ib);
                    u32 a = acc[j];
                    a = hfma2u(cc.x, xa, a);
                    a = hfma2u(cc.y, xb, a);
                    a = hfma2u(cc.z, xc, a);
                    a = hfma2u(cc.w, xd, a);
                    acc[j] = a;
                }
            }
            // combine 4 code-pairs -> packed scores, insert into top-12
            #pragma unroll
            for (int jp = 0; jp < 4; ++jp) {
                u32 a = acc[2 * jp], b = acc[2 * jp + 1];
                u32 da = hadd2u(a, __byte_perm(a, a, 0x1032));  // lo+hi both halves
                u32 db = hadd2u(b, __byte_perm(b, b, 0x1032));
                u32 dd = __byte_perm(da, db, 0x5410);           // (da.h0, db.h0)
                u32 sc = hfma2u(dd, MINUS2H2, c2h[(kb >> 1) + jp]); // c2 - 2*dot
                u32 e0 = sc & 0xFFFFu, e1 = sc >> 16;
                u32 o0 = e0 ^ (0x8000u + (e0 >> 15) * 0x7FFFu); // order-preserving u16
                u32 o1 = e1 ^ (0x8000u + (e1 >> 15) * 0x7FFFu);
                trk_insert(trk, (o0 << 16) | (u32)(kb + 2 * jp));
                trk_insert(trk, (o1 << 16) | (u32)(kb + 2 * jp + 1));
            }
        }

        // ---- decode screen scores ----
        float sdec[NTRK];
        #pragma unroll
        for (int i = 0; i < NTRK; ++i) {
            u32 o = trk[i] >> 16;
            u32 bbits = (o & 0x8000u) ? (o ^ 0x8000u) : ((~o) & 0xFFFFu);
            sdec[i] = __half2float(__ushort_as_half((unsigned short)bbits));
        }
        const float lim = sdec[0] + WIN;

        int bestk = (int)(trk[0] & 0xFFFFu);
        if (sdec[1] <= lim) {
            // exact rescore path: reload fp32 row, reference-order arithmetic
            float xl[DIMV];
            #pragma unroll
            for (int i = 0; i < 16; ++i) ((float4*)xl)[i] = lp[i];
            float x2 = 0.f;
            #pragma unroll
            for (int d = 0; d < DIMV; ++d) x2 = __fadd_rn(x2, __fmul_rn(xl[d], xl[d]));

            if (sdec[NTRK - 1] <= lim) {
                // tracker may have overflowed: full exact first-min scan, ILP-2
                float best = 3.4e38f; bestk = 0;
                for (int k = 0; k < K_CODES; k += 2) {
                    const float* c0 = scb + k * DIMV;
                    const float* c1 = c0 + DIMV;
                    float m0 = 0.f, m1 = 0.f;
                    #pragma unroll
                    for (int d = 0; d < DIMV; ++d) {
                        m0 = __fmaf_rn(xl[d], c0[d], m0);
                        m1 = __fmaf_rn(xl[d], c1[d], m1);
                    }
                    float e0 = __fadd_rn(__fadd_rn(x2, -2.f * m0), sc2[k]);
                    float e1 = __fadd_rn(__fadd_rn(x2, -2.f * m1), sc2[k + 1]);
                    if (e0 < best) { best = e0; bestk = k; }
                    if (e1 < best) { best = e1; bestk = k + 1; }
                }
            } else {
                float ebest = 3.4e38f; bestk = K_CODES;
                #pragma unroll
                for (int i = 0; i < NTRK; ++i) {
                    if (sdec[i] <= lim) {
                        int k = (int)(trk[i] & 0xFFFFu);
                        const float* c = scb + k * DIMV;
                        float m = 0.f;
                        #pragma unroll
                        for (int d = 0; d < DIMV; ++d) m = __fmaf_rn(xl[d], c[d], m);
                        float e = __fadd_rn(__fadd_rn(x2, -2.f * m), sc2[k]);
                        if (e < ebest || (e == ebest && k < bestk)) { ebest = e; bestk = k; }
                    }
                }
            }
        }

        // ---- epilogue: ST output (reference roundings) + loss + hist ----
        float* qout = out + (size_t)row * DIMV;
        const float4* cq = (const float4*)(scb + bestk * DIMV);
        float rowsq = 0.f;
        #pragma unroll
        for (int i = 0; i < 16; ++i) {
            float4 l = lp[i];
            float4 q = cq[i];
            float4 o;
            o.x = __fadd_rn(l.x, __fsub_rn(q.x, l.x));
            o.y = __fadd_rn(l.y, __fsub_rn(q.y, l.y));
            o.z = __fadd_rn(l.z, __fsub_rn(q.z, l.z));
            o.w = __fadd_rn(l.w, __fsub_rn(q.w, l.w));
            ((float4*)qout)[i] = o;
            float dx = l.x - q.x, dy = l.y - q.y, dz = l.z - q.z, dw = l.w - q.w;
            rowsq = fmaf(dx, dx, rowsq);
            rowsq = fmaf(dy, dy, rowsq);
            rowsq = fmaf(dz, dz, rowsq);
            rowsq = fmaf(dw, dw, rowsq);
        }
        out[(size_t)NROWS * DIMV + row] = (float)bestk;
        atomicAdd(&shist[bestk], 1);
        sqAcc += rowsq;
    }

    // ---- reductions ----
    sred[tid] = sqAcc;
    __syncthreads();
    for (int s = TPB / 2; s > 0; s >>= 1) {
        if (tid < s) sred[tid] += sred[tid + s];
        __syncthreads();
    }
    if (tid == 0) atomicAdd(&g_sqsum, (double)sred[0]);
    for (int k = tid; k < K_CODES; k += TPB) {
        int c = shist[k];
        if (c) atomicAdd(&g_counts[k], c);
    }
}

__global__ void vq_finalize_kernel(float* __restrict__ out) {
    __shared__ float red[K_CODES];
    int t = threadIdx.x;
    float p = (float)g_counts[t] / (float)NROWS;
    red[t] = -p * logf(p + 1e-10f);
    __syncthreads();
    for (int s = K_CODES / 2; s > 0; s >>= 1) {
        if (t < s) red[t] += red[t + s];
        __syncthreads();
    }
    if (t == 0) {
        float perp = expf(red[0]);
        float msd = (float)(g_sqsum / (double)((size_t)NROWS * DIMV));
        size_t base = (size_t)NROWS * DIMV + NROWS;
        out[base + 0] = msd * 0.25f;   // commitment * COMMITMENT_COST
        out[base + 1] = msd;           // codebook loss
        out[base + 2] = perp;          // perplexity
    }
}

extern "C" void kernel_launch(void* const* d_in, const int* in_sizes, int n_in,
                              void* d_out, int out_size) {
    (void)in_sizes; (void)n_in; (void)out_size;
    const float* latents  = (const float*)d_in[0];
    const float* codebook = (const float*)d_in[1];
    float* out = (float*)d_out;

    const int smem_bytes = SMEM_WORDS * 4;
    cudaFuncSetAttribute(vq_main_kernel,
                         cudaFuncAttributeMaxDynamicSharedMemorySize, smem_bytes);

    vq_init_kernel<<<2, 256>>>();
    vq_main_kernel<<<NBLK, TPB, smem_bytes>>>(latents, codebook, out);
    vq_finalize_kernel<<<1, K_CODES>>>(out);
}

// round 15
// speedup vs baseline: 1.0044x; 1.0044x over previous
#include <cuda_runtime.h>
#include <math.h>
#include <stdint.h>

// VectorQuantizer: N=131072 rows (dim 64) vs 512 codes.
// Quarter-row decomposition: each row's 512 codes split across 4 threads
// (interleaved k = 4j+q), so 524288 units over 75776 threads -> 98.9% balance.
// Screen ranks by t = m - c2/2 (chain init -c2/2, exact same fma order as the
// reference chain); per-code argmin tracking runs entirely on the ALU pipe
// (order-transformed u32 keys, index embedded in low 9 bits, IMNMX top-3).
// Groups with merged top-2 t-gap <= WT get the bitwise-exact reference
// rescore (sequential chain, round(round(x2-2m)+c2), first-min).
// Out (fp32): [0,8388608) quantized_st; [8388608,8519680) codes;
//             then commitment*0.25, codebook_loss, perplexity.
#define K_CODES 512
#define DIMV 64
#define NROWS 131072
#define TPB 512
#define NBLK 148
#define NIT 7              // ceil(886/128)
#define CBS 68             // padded codebook stride (words)
#define WT 8e-5f           // ambiguity window on t (score gap 1.6e-4)

typedef unsigned int u32;

// smem word offsets
#define W_CB   0                       // padded fp32 codebook 512*68
#define W_NH   (K_CODES * CBS)         // neghalf c2 [512]
#define W_HIST (W_NH + K_CODES)        // int [512]
#define W_SRED (W_HIST + K_CODES)      // float [TPB]
#define SMEM_WORDS (W_SRED + TPB)

__device__ double g_sqsum;
__device__ int g_counts[K_CODES];

__global__ void vq_init_kernel() {
    int t = blockIdx.x * blockDim.x + threadIdx.x;
    if (t == 0) g_sqsum = 0.0;
    if (t < K_CODES) g_counts[t] = 0;
}

// order-preserving float-bits -> ascending unsigned
__device__ __forceinline__ u32 f2o(float f) {
    int i = __float_as_int(f);
    return (u32)i ^ (u32)((i >> 31) | 0x80000000);
}
__device__ __forceinline__ float o2f(u32 u) {
    int i = (u & 0x80000000u) ? (int)(u ^ 0x80000000u) : (int)~u;
    return __int_as_float(i);
}

__global__ __launch_bounds__(TPB, 1)
void vq_main_kernel(const float* __restrict__ latents,
                    const float* __restrict__ codebook,
                    float* __restrict__ out) {
    extern __shared__ float smem[];
    float* cbf  = smem + W_CB;
    float* nh   = smem + W_NH;
    int*  shist = (int*)(smem + W_HIST);
    float* sred = smem + W_SRED;

    const int tid = threadIdx.x;
    const int g = tid >> 2;        // row group 0..127
    const int q = tid & 3;         // quarter 0..3
    const int lanebase = (tid & 31) & ~3;

    // ---- prologue: padded codebook + reference-order c2 -> -c2/2 ----
    const float4* cb4 = (const float4*)codebook;
    for (int g2 = tid; g2 < K_CODES * 16; g2 += TPB) {
        int k = g2 >> 4, i = g2 & 15;
        *(float4*)(cbf + k * CBS + i * 4) = cb4[g2];
    }
    for (int k = tid; k < K_CODES; k += TPB) shist[k] = 0;
    __syncthreads();
    for (int k = tid; k < K_CODES; k += TPB) {
        const float* c = cbf + k * CBS;
        float s = 0.f;
        #pragma unroll
        for (int d = 0; d < DIMV; ++d) s = __fadd_rn(s, __fmul_rn(c[d], c[d]));
        nh[k] = -0.5f * s;         // exact halving
    }
    __syncthreads();

    const int r0 = (int)(((long long)NROWS * blockIdx.x) / NBLK);
    const int r1 = (int)(((long long)NROWS * (blockIdx.x + 1)) / NBLK);
    float sqAcc = 0.f;

    for (int it = 0; it < NIT; ++it) {
        const int row = r0 + g + it * 128;
        const bool valid = row < r1;
        const int rld = valid ? row : r0;

        // full latent row in registers (all 4 quarter-threads need all dims)
        float4 xv[16];
        const float4* lp = (const float4*)(latents + (size_t)rld * DIMV);
        #pragma unroll
        for (int i = 0; i < 16; ++i) xv[i] = lp[i];

        // ---- screen: 128 codes (k = 4j+q), chains init -c2/2 ----
        u32 key1 = 0u, key2 = 0u, key3 = 0u;   // max-keys; 0 == -inf
        for (int jb = 0; jb < 16; ++jb) {
            const int kbase = 32 * jb + q;     // codes kbase + 4m, m=0..7
            float acc[8];
            #pragma unroll
            for (int m = 0; m < 8; ++m) acc[m] = nh[kbase + 4 * m];
            #pragma unroll
            for (int dv = 0; dv < 16; ++dv) {
                const float4 xd = xv[dv];
                #pragma unroll
                for (int m = 0; m < 8; ++m) {
                    const float4 cd = *(const float4*)(cbf + (kbase + 4 * m) * CBS + dv * 4);
                    float a = acc[m];
                    a = __fmaf_rn(xd.x, cd.x, a);
                    a = __fmaf_rn(xd.y, cd.y, a);
                    a = __fmaf_rn(xd.z, cd.z, a);
                    a = __fmaf_rn(xd.w, cd.w, a);
                    acc[m] = a;
                }
            }
            #pragma unroll
            for (int m = 0; m < 8; ++m) {
                const int k = kbase + 4 * m;
                u32 key = (f2o(acc[m]) & 0xFFFFFE00u) | (0x1FFu ^ (u32)k);
                key3 = max(key3, min(key, key2));   // IMNMX, ALU pipe
                key2 = max(key2, min(key, key1));
                key1 = max(key1, key);
            }
        }

        // ---- merge top-3 across the 4 quarter-lanes (same row) ----
        #pragma unroll
        for (int m = 1; m <= 2; m <<= 1) {
            u32 b1 = __shfl_xor_sync(0xffffffffu, key1, m);
            u32 b2 = __shfl_xor_sync(0xffffffffu, key2, m);
            u32 b3 = __shfl_xor_sync(0xffffffffu, key3, m);
            u32 lo1 = min(key1, b1), hi22 = max(key2, b2);
            u32 n1 = max(key1, b1);
            u32 n2 = max(lo1, hi22);
            u32 n3 = max(max(min(lo1, hi22), max(key3, b3)), min(key2, b2));
            key1 = n1; key2 = n2; key3 = n3;
        }

        int bestk = (int)(0x1FFu ^ (key1 & 0x1FFu));
        const float t1 = o2f(key1), t2 = o2f(key2), t3 = o2f(key3);

        // ---- ambiguous: bitwise-exact reference rescore (lane q==0) ----
        if (valid && q == 0 && (t1 - t2 <= WT)) {
            float x2 = 0.f;
            #pragma unroll
            for (int i = 0; i < 16; ++i) {
                x2 = __fadd_rn(x2, __fmul_rn(xv[i].x, xv[i].x));
                x2 = __fadd_rn(x2, __fmul_rn(xv[i].y, xv[i].y));
                x2 = __fadd_rn(x2, __fmul_rn(xv[i].z, xv[i].z));
                x2 = __fadd_rn(x2, __fmul_rn(xv[i].w, xv[i].w));
            }
            if (t1 - t3 <= WT) {
                // very rare: full exact first-min scan
                float best = 3.4e38f; bestk = 0;
                for (int k = 0; k < K_CODES; ++k) {
                    const float* c = cbf + k * CBS;
                    float mchain = 0.f;
                    #pragma unroll
                    for (int d = 0; d < DIMV; ++d) mchain = __fmaf_rn(
                        ((const float*)xv)[d], c[d], mchain);
                    float c2 = -2.f * nh[k];
                    float e = __fadd_rn(__fadd_rn(x2, -2.f * mchain), c2);
                    if (e < best) { best = e; bestk = k; }
                }
            } else {
                int ka = (int)(0x1FFu ^ (key1 & 0x1FFu));
                int kb = (int)(0x1FFu ^ (key2 & 0x1FFu));
                const float* ca = cbf + ka * CBS;
                const float* cb = cbf + kb * CBS;
                float ma = 0.f, mb = 0.f;
                #pragma unroll
                for (int d = 0; d < DIMV; ++d) {
                    float xd = ((const float*)xv)[d];
                    ma = __fmaf_rn(xd, ca[d], ma);
                    mb = __fmaf_rn(xd, cb[d], mb);
                }
                float ea = __fadd_rn(__fadd_rn(x2, -2.f * ma), -2.f * nh[ka]);
                float eb = __fadd_rn(__fadd_rn(x2, -2.f * mb), -2.f * nh[kb]);
                bestk = ka;
                if (eb < ea || (eb == ea && kb < ka)) bestk = kb;
            }
        }
        bestk = __shfl_sync(0xffffffffu, bestk, lanebase);  // uniform: all lanes

        // ---- epilogue: each quarter-lane writes its 16-dim quadrant ----
        if (valid) {
            float* qout = out + (size_t)row * DIMV + q * 16;
            const float* cq = cbf + bestk * CBS + q * 16;
            #pragma unroll
            for (int i = 0; i < 4; ++i) {
                float4 l = xv[q * 4 + i];
                float4 c = *(const float4*)(cq + i * 4);
                float4 o;
                o.x = __fadd_rn(l.x, __fsub_rn(c.x, l.x));
                o.y = __fadd_rn(l.y, __fsub_rn(c.y, l.y));
                o.z = __fadd_rn(l.z, __fsub_rn(c.z, l.z));
                o.w = __fadd_rn(l.w, __fsub_rn(c.w, l.w));
                ((float4*)qout)[i] = o;
                float dx = l.x - c.x, dy = l.y - c.y, dz = l.z - c.z, dw = l.w - c.w;
                sqAcc = fmaf(dx, dx, sqAcc);
                sqAcc = fmaf(dy, dy, sqAcc);
                sqAcc = fmaf(dz, dz, sqAcc);
                sqAcc = fmaf(dw, dw, sqAcc);
            }
            if (q == 0) {
                out[(size_t)NROWS * DIMV + row] = (float)bestk;
                atomicAdd(&shist[bestk], 1);
            }
        }
    }

    // ---- reductions ----
    sred[tid] = sqAcc;
    __syncthreads();
    for (int s = TPB / 2; s > 0; s >>= 1) {
        if (tid < s) sred[tid] += sred[tid + s];
        __syncthreads();
    }
    if (tid == 0) atomicAdd(&g_sqsum, (double)sred[0]);
    for (int k = tid; k < K_CODES; k += TPB) {
        int c = shist[k];
        if (c) atomicAdd(&g_counts[k], c);
    }
}

__global__ void vq_finalize_kernel(float* __restrict__ out) {
    __shared__ float red[K_CODES];
    int t = threadIdx.x;
    float p = (float)g_counts[t] / (float)NROWS;
    red[t] = -p * logf(p + 1e-10f);
    __syncthreads();
    for (int s = K_CODES / 2; s > 0; s >>= 1) {
        if (t < s) red[t] += red[t + s];
        __syncthreads();
    }
    if (t == 0) {
        float perp = expf(red[0]);
        float msd = (float)(g_sqsum / (double)((size_t)NROWS * DIMV));
        size_t base = (size_t)NROWS * DIMV + NROWS;
        out[base + 0] = msd * 0.25f;   // commitment * COMMITMENT_COST
        out[base + 1] = msd;           // codebook loss
        out[base + 2] = perp;          // perplexity
    }
}

extern "C" void kernel_launch(void* const* d_in, const int* in_sizes, int n_in,
                              void* d_out, int out_size) {
    (void)in_sizes; (void)n_in; (void)out_size;
    const float* latents  = (const float*)d_in[0];
    const float* codebook = (const float*)d_in[1];
    float* out = (float*)d_out;

    const int smem_bytes = SMEM_WORDS * 4;
    cudaFuncSetAttribute(vq_main_kernel,
                         cudaFuncAttributeMaxDynamicSharedMemorySize, smem_bytes);

    vq_init_kernel<<<2, 256>>>();
    vq_main_kernel<<<NBLK, TPB, smem_bytes>>>(latents, codebook, out);
    vq_finalize_kernel<<<1, K_CODES>>>(out);
}